// round 16
// baseline (speedup 1.0000x reference)
#include <cuda_runtime.h>
#include <cuda_fp16.h>
#include <cstdint>
#include <math.h>

// ---------------- problem constants ----------------
#define HNUM 16
#define CDIM 4096
#define HD 64
#define BB 4
#define SS 256
#define DIN 1024
#define ATT 1024
#define RR 256
#define CRN 1024
#define SCN 2048
#define FFN 3072
#define EPSV 1e-5f
#define CW 2048            // c-chunk width (2 chunks)

// ---------------- device scratch ----------------
__device__ __align__(16) float g_q[HNUM*CDIM*HD];
__device__ __align__(16) float g_qdet[HNUM*CDIM*HD];
__device__ __align__(16) float g_qr[HNUM*RR*HD];
__device__ __align__(16) float g_kvraw[BB*SS*2*ATT];
__device__ __align__(16) float g_k[BB*HNUM*SS*HD];
__device__ __align__(16) float g_v[BB*HNUM*SS*HD];
__device__ __align__(16) float g_o[BB*CDIM*ATT];
__device__ __align__(16) float g_z[BB*CDIM*ATT];

__device__ __align__(16) __half g_xhi[BB*SS*DIN],   g_xlo[BB*SS*DIN];
__device__ __align__(16) __half g_kvwh[2*ATT*DIN],  g_kvwl[2*ATT*DIN];
__device__ __align__(16) __half g_lnh[BB*CDIM*ATT];
__device__ __align__(16) __half g_ffinh[2*FFN*ATT];
__device__ __align__(16) __half g_gh[(size_t)BB*CDIM*FFN];
__device__ __align__(16) __half g_ffouth[ATT*FFN];

__device__ __forceinline__ float warp_sum(float v){
    #pragma unroll
    for (int o = 16; o; o >>= 1) v += __shfl_xor_sync(0xffffffffu, v, o);
    return v;
}
__device__ __forceinline__ float warp_max(float v){
    #pragma unroll
    for (int o = 16; o; o >>= 1) v = fmaxf(v, __shfl_xor_sync(0xffffffffu, v, o));
    return v;
}

// packed f32x2 helpers
#define PACK2(out, lo, hi) asm("mov.b64 %0, {%1, %2};" : "=l"(out) : "f"(lo), "f"(hi))
#define UNPACK2(lo, hi, in) asm("mov.b64 {%0, %1}, %2;" : "=f"(lo), "=f"(hi) : "l"(in))
#define FMA2(d, a, b, c) asm("fma.rn.f32x2 %0, %1, %2, %3;" : "=l"(d) : "l"(a), "l"(b), "l"(c))

__global__ void copy4_kernel(const float4* __restrict__ src, float4* __restrict__ dst, int n4){
    int i = blockIdx.x * blockDim.x + threadIdx.x;
    if (i < n4) dst[i] = src[i];
}

__global__ void split_kernel(const float4* __restrict__ in, __half* __restrict__ hi,
                             __half* __restrict__ lo, int n4){
    int i = blockIdx.x * blockDim.x + threadIdx.x;
    if (i >= n4) return;
    float4 v = in[i];
    float vv[4] = {v.x, v.y, v.z, v.w};
    __half h[4], l[4];
    #pragma unroll
    for (int j = 0; j < 4; j++){
        h[j] = __float2half(vv[j]);
        l[j] = __float2half(vv[j] - __half2float(h[j]));
    }
    *(uint2*)&hi[(size_t)i*4] = *(uint2*)h;
    *(uint2*)&lo[(size_t)i*4] = *(uint2*)l;
}

__global__ void conv_half_kernel(const float4* __restrict__ in, __half* __restrict__ out, int n4){
    int i = blockIdx.x * blockDim.x + threadIdx.x;
    if (i >= n4) return;
    float4 v = in[i];
    __half h[4] = {__float2half(v.x), __float2half(v.y), __float2half(v.z), __float2half(v.w)};
    *(uint2*)&out[(size_t)i*4] = *(uint2*)h;
}

__global__ void conv_ffin_kernel(const float4* __restrict__ in, __half* __restrict__ out, int n4){
    int i = blockIdx.x * blockDim.x + threadIdx.x;
    if (i >= n4) return;
    int e = i * 4;
    int rout = e >> 10;
    int c = e & 1023;
    int rin = (rout & 1) ? (FFN + (rout >> 1)) : (rout >> 1);
    float4 v = in[((size_t)rin << 10 | c) >> 2];
    __half h[4] = {__float2half(v.x), __float2half(v.y), __float2half(v.z), __float2half(v.w)};
    *(uint2*)&out[(size_t)rout*1024 + c] = *(uint2*)h;
}

__global__ void rms64_kernel(const float* __restrict__ in, float* __restrict__ out){
    int row = blockIdx.x, t = threadIdx.x;
    float2 v = ((const float2*)(in + (size_t)row*64))[t];
    float ss = v.x*v.x + v.y*v.y;
    ss = warp_sum(ss);
    float sc = rsqrtf(ss*(1.f/64.f) + EPSV);
    ((float2*)(out + (size_t)row*64))[t] = make_float2(v.x*sc, v.y*sc);
}

__global__ void scatter_kernel(const int* __restrict__ srcidx, const int* __restrict__ dstidx,
                               const float* __restrict__ w, const float* __restrict__ src,
                               float* __restrict__ dst, int nper, int src_rows){
    int j = blockIdx.x % nper;
    int h = blockIdx.x / nper;
    int r = srcidx[j];
    int c = dstidx[j];
    float ww = w[(size_t)h*nper + j];
    int t = threadIdx.x;
    atomicAdd(&dst[((size_t)h*CDIM + c)*64 + t], src[((size_t)h*src_rows + r)*64 + t] * ww);
}

__global__ void kvsplit_kernel(const float* __restrict__ kvraw, float* __restrict__ kout,
                               float* __restrict__ vout){
    int bid = blockIdx.x;
    int t = threadIdx.x;
    int b = bid >> 12, h = (bid >> 8) & 15, s = bid & 255;
    size_t rowoff = ((size_t)(b*SS + s))*2048 + h*64;
    float2 kv = ((const float2*)(kvraw + rowoff))[t];
    float2 vv = ((const float2*)(kvraw + rowoff + 1024))[t];
    float ss = kv.x*kv.x + kv.y*kv.y;
    ss = warp_sum(ss);
    float sc = rsqrtf(ss*(1.f/64.f) + EPSV);
    ((float2*)(kout + (size_t)bid*64))[t] = make_float2(kv.x*sc, kv.y*sc);
    ((float2*)(vout + (size_t)bid*64))[t] = vv;
}

// ---------------- common GEMM pieces ----------------
#define GR 40
#define BUF_BYTES (128*GR*2)
#define GEMM_SMEM_4 (2*4*BUF_BYTES)

__device__ __forceinline__ void mma16816(float* d, const unsigned int* a, const unsigned int* b){
    asm volatile(
        "mma.sync.aligned.m16n8k16.row.col.f32.f16.f16.f32 "
        "{%0,%1,%2,%3}, {%4,%5,%6,%7}, {%8,%9}, {%0,%1,%2,%3};\n"
        : "+f"(d[0]), "+f"(d[1]), "+f"(d[2]), "+f"(d[3])
        : "r"(a[0]), "r"(a[1]), "r"(a[2]), "r"(a[3]), "r"(b[0]), "r"(b[1]));
}
__device__ __forceinline__ void ldsm_x4(unsigned int& r0, unsigned int& r1,
                                        unsigned int& r2, unsigned int& r3, unsigned int addr){
    asm volatile("ldmatrix.sync.aligned.m8n8.x4.shared.b16 {%0,%1,%2,%3}, [%4];"
                 : "=r"(r0), "=r"(r1), "=r"(r2), "=r"(r3) : "r"(addr));
}
__device__ __forceinline__ void cpasync16(unsigned int saddr, const void* g){
    asm volatile("cp.async.cg.shared.global [%0], [%1], 16;" :: "r"(saddr), "l"(g));
}

// ---------------- kv GEMM: 3-product, 128x128 tile ----------------
__global__ void __launch_bounds__(256) gemm_kv(
    const __half* __restrict__ Ahi, const __half* __restrict__ Alo,
    const __half* __restrict__ Bhi, const __half* __restrict__ Blo,
    float* __restrict__ C, int M, int N, int K)
{
    extern __shared__ __half smem[];
    float acc[2][8][4] = {};
    const int tid = threadIdx.x;
    const int bm = blockIdx.y << 7, bn = blockIdx.x << 7;
    const int warp = tid >> 5, lane = tid & 31;
    const int g = lane >> 2, tg = lane & 3;
    const int wm = (warp >> 1) << 5, wn = (warp & 1) << 6;
    unsigned int sbase = (unsigned int)__cvta_generic_to_shared(smem);
    const __half* gah = Ahi + (size_t)bm*K;
    const __half* gal = Alo + (size_t)bm*K;
    const __half* gbh = Bhi + (size_t)bn*K;
    const __half* gbl = Blo + (size_t)bn*K;
    const int lr = tid >> 2, lc = (tid & 3) << 3;

    auto load_stage = [&](int k0, int s){
        unsigned int sb = sbase + s*4*BUF_BYTES;
        #pragma unroll
        for (int half_i = 0; half_i < 2; half_i++){
            int r = lr + (half_i << 6);
            size_t go = (size_t)r*K + k0 + lc;
            unsigned int so = (unsigned int)(r*GR + lc)*2;
            cpasync16(sb + so, gah + go);
            cpasync16(sb + 1*BUF_BYTES + so, gal + go);
            cpasync16(sb + 2*BUF_BYTES + so, gbh + go);
            cpasync16(sb + 3*BUF_BYTES + so, gbl + go);
        }
        asm volatile("cp.async.commit_group;");
    };

    load_stage(0, 0);
    const int nIt = K >> 5;
    for (int it = 0; it < nIt; it++){
        int s = it & 1;
        if (it + 1 < nIt){
            load_stage((it + 1) << 5, s ^ 1);
            asm volatile("cp.async.wait_group 1;");
        } else {
            asm volatile("cp.async.wait_group 0;");
        }
        __syncthreads();
        unsigned int sAh = sbase + (s*4 + 0)*BUF_BYTES;
        unsigned int sAl = sbase + (s*4 + 1)*BUF_BYTES;
        unsigned int sBh = sbase + (s*4 + 2)*BUF_BYTES;
        unsigned int sBl = sbase + (s*4 + 3)*BUF_BYTES;
        #pragma unroll
        for (int kg = 0; kg < 2; kg++){
            unsigned int ah[2][4], al[2][4];
            unsigned int aoff = (unsigned int)((wm + (lane & 15))*80 + kg*32 + ((lane >> 4) << 4));
            ldsm_x4(ah[0][0], ah[0][1], ah[0][2], ah[0][3], sAh + aoff);
            ldsm_x4(ah[1][0], ah[1][1], ah[1][2], ah[1][3], sAh + aoff + 16*80);
            ldsm_x4(al[0][0], al[0][1], al[0][2], al[0][3], sAl + aoff);
            ldsm_x4(al[1][0], al[1][1], al[1][2], al[1][3], sAl + aoff + 16*80);
            #pragma unroll
            for (int np = 0; np < 4; np++){
                unsigned int boff = (unsigned int)(
                    (wn + np*16 + (lane & 7) + ((lane >> 4) << 3))*80
                    + kg*32 + (((lane >> 3) & 1) << 4));
                unsigned int bh[4], bl[4];
                ldsm_x4(bh[0], bh[1], bh[2], bh[3], sBh + boff);
                ldsm_x4(bl[0], bl[1], bl[2], bl[3], sBl + boff);
                #pragma unroll
                for (int mt = 0; mt < 2; mt++){
                    mma16816(acc[mt][np*2], ah[mt], bh);
                    mma16816(acc[mt][np*2], al[mt], bh);
                    mma16816(acc[mt][np*2], ah[mt], bl);
                    mma16816(acc[mt][np*2 + 1], ah[mt], bh + 2);
                    mma16816(acc[mt][np*2 + 1], al[mt], bh + 2);
                    mma16816(acc[mt][np*2 + 1], ah[mt], bl + 2);
                }
            }
        }
        __syncthreads();
    }
    #pragma unroll
    for (int mt = 0; mt < 2; mt++){
        #pragma unroll
        for (int nt = 0; nt < 8; nt++){
            size_t row0 = (size_t)bm + wm + (mt << 4) + g;
            int col = bn + wn + (nt << 3) + (tg << 1);
            *(float2*)&C[row0*N + col]      = make_float2(acc[mt][nt][0], acc[mt][nt][1]);
            *(float2*)&C[(row0+8)*N + col]  = make_float2(acc[mt][nt][2], acc[mt][nt][3]);
        }
    }
}

// ---------------- single-product GEMM, 128x256 tile (chunked M map) ----------------
#define ABUF256 (128*GR*2)
#define BBUF256 (256*GR*2)
#define STG256 (ABUF256 + BBUF256)
#define GEMM256_SMEM (2*STG256)

__device__ __forceinline__ void gemm256_mainloop(
    const __half* __restrict__ Ah, const __half* __restrict__ Bh,
    int K, int bm, int bn, float acc[4][8][4], __half* smem)
{
    const int tid = threadIdx.x;
    const int warp = tid >> 5, lane = tid & 31;
    const int wm = (warp >> 2) << 6;
    const int wn = (warp & 3) << 6;
    unsigned int sbase = (unsigned int)__cvta_generic_to_shared(smem);
    const __half* ga = Ah + (size_t)bm*K;
    const __half* gb = Bh + (size_t)bn*K;
    const int lr = tid >> 2, lc = (tid & 3) << 3;

    auto load_stage = [&](int k0, int s){
        unsigned int sb = sbase + s*STG256;
        #pragma unroll
        for (int p = 0; p < 2; p++){
            int r = lr + (p << 6);
            size_t go = (size_t)r*K + k0 + lc;
            unsigned int so = (unsigned int)(r*GR + lc)*2;
            cpasync16(sb + so, ga + go);
        }
        #pragma unroll
        for (int p = 0; p < 4; p++){
            int r = lr + (p << 6);
            size_t go = (size_t)r*K + k0 + lc;
            unsigned int so = (unsigned int)(r*GR + lc)*2;
            cpasync16(sb + ABUF256 + so, gb + go);
        }
        asm volatile("cp.async.commit_group;");
    };

    load_stage(0, 0);
    const int nIt = K >> 5;
    for (int it = 0; it < nIt; it++){
        int s = it & 1;
        if (it + 1 < nIt){
            load_stage((it + 1) << 5, s ^ 1);
            asm volatile("cp.async.wait_group 1;");
        } else {
            asm volatile("cp.async.wait_group 0;");
        }
        __syncthreads();
        unsigned int sA = sbase + s*STG256;
        unsigned int sB = sA + ABUF256;
        #pragma unroll
        for (int kg = 0; kg < 2; kg++){
            unsigned int ah[4][4];
            unsigned int aoff = (unsigned int)((wm + (lane & 15))*80 + kg*32 + ((lane >> 4) << 4));
            ldsm_x4(ah[0][0], ah[0][1], ah[0][2], ah[0][3], sA + aoff);
            ldsm_x4(ah[1][0], ah[1][1], ah[1][2], ah[1][3], sA + aoff + 16*80);
            ldsm_x4(ah[2][0], ah[2][1], ah[2][2], ah[2][3], sA + aoff + 32*80);
            ldsm_x4(ah[3][0], ah[3][1], ah[3][2], ah[3][3], sA + aoff + 48*80);
            #pragma unroll
            for (int np = 0; np < 4; np++){
                unsigned int boff = (unsigned int)(
                    (wn + np*16 + (lane & 7) + ((lane >> 4) << 3))*80
                    + kg*32 + (((lane >> 3) & 1) << 4));
                unsigned int bh[4];
                ldsm_x4(bh[0], bh[1], bh[2], bh[3], sB + boff);
                #pragma unroll
                for (int mt = 0; mt < 4; mt++){
                    mma16816(acc[mt][np*2],     ah[mt], bh);
                    mma16816(acc[mt][np*2 + 1], ah[mt], bh + 2);
                }
            }
        }
        __syncthreads();
    }
}

// chunked M map: blockIdx.y covers BB batches x (CW/128) tiles within c-chunk
__device__ __forceinline__ int chunk_bm(int by, int cbase){
    return ((by >> 4) << 12) + cbase + ((by & 15) << 7);   // CW=2048 -> 16 tiles per batch
}

__global__ void __launch_bounds__(256) gemm_nt_addo256(
    const __half* __restrict__ Ah, const __half* __restrict__ Bh,
    const float* __restrict__ O,
    float* __restrict__ Z, int N, int K, int cbase)
{
    extern __shared__ __half smem[];
    float acc[4][8][4] = {};
    const int tid = threadIdx.x;
    const int bm = chunk_bm(blockIdx.y, cbase), bn = blockIdx.x << 8;
    const int warp = tid >> 5, lane = tid & 31;
    const int g = lane >> 2, tg = lane & 3;
    const int wm = (warp >> 2) << 6, wn = (warp & 3) << 6;
    gemm256_mainloop(Ah, Bh, K, bm, bn, acc, smem);
    #pragma unroll
    for (int mt = 0; mt < 4; mt++){
        #pragma unroll
        for (int nt = 0; nt < 8; nt++){
            size_t row0 = (size_t)bm + wm + (mt << 4) + g;
            int col = bn + wn + (nt << 3) + (tg << 1);
            float2 o0 = *(const float2*)&O[row0*N + col];
            float2 o1 = *(const float2*)&O[(row0+8)*N + col];
            *(float2*)&Z[row0*N + col]     = make_float2(acc[mt][nt][0] + o0.x, acc[mt][nt][1] + o0.y);
            *(float2*)&Z[(row0+8)*N + col] = make_float2(acc[mt][nt][2] + o1.x, acc[mt][nt][3] + o1.y);
        }
    }
}

#define GSR256 132
__global__ void __launch_bounds__(256) gemm_ff1_gate256(
    const __half* __restrict__ Ah, const __half* __restrict__ Bh,
    __half* __restrict__ Gh, int N, int K, int cbase)
{
    extern __shared__ __half smem[];
    float acc[4][8][4] = {};
    const int tid = threadIdx.x;
    const int bm = chunk_bm(blockIdx.y, cbase), bn = blockIdx.x << 8;
    const int warp = tid >> 5, lane = tid & 31;
    const int g = lane >> 2, tg = lane & 3;
    const int wm = (warp >> 2) << 6, wn = (warp & 3) << 6;
    gemm256_mainloop(Ah, Bh, K, bm, bn, acc, smem);
    __half* sh = smem;
    #pragma unroll
    for (int mt = 0; mt < 4; mt++){
        #pragma unroll
        for (int nt = 0; nt < 8; nt++){
            int rl = wm + (mt << 4) + g;
            int oc = (wn >> 1) + (nt << 2) + tg;
            float f1a = acc[mt][nt][0], f2a = acc[mt][nt][1];
            float f1b = acc[mt][nt][2], f2b = acc[mt][nt][3];
            float ga = f1a / (1.f + __expf(-f1a)) * f2a;
            float gb = f1b / (1.f + __expf(-f1b)) * f2b;
            sh[rl*GSR256 + oc]     = __float2half(ga);
            sh[(rl+8)*GSR256 + oc] = __float2half(gb);
        }
    }
    __syncthreads();
    int gc0 = bn >> 1;
    #pragma unroll
    for (int idx = tid; idx < 4096; idx += 256){
        int row = idx >> 5, c4 = (idx & 31) << 2;
        size_t go = (size_t)(bm + row)*FFN + gc0 + c4;
        *(uint2*)&Gh[go] = *(uint2*)&sh[row*GSR256 + c4];
    }
}

// ---------------- attention: 8 c per iter, f32x2 packed FMA, chunked ----------------
#define SROW 68
#define ATTN_SMEM ((2*256*SROW + 512 + 2048 + 2048 + 128) * 4)
__global__ void __launch_bounds__(256) attn_kernel(const float* __restrict__ q,
                                                   const float* __restrict__ k,
                                                   const float* __restrict__ v,
                                                   float* __restrict__ o, int cbase){
    extern __shared__ float sm[];
    float* ks = sm;
    float* vs = ks + 256*SROW;
    float* qs2 = vs + 256*SROW;
    float* at2 = qs2 + 512;
    float* op  = at2 + 2048;
    float* rd  = op + 2048;
    int tid = threadIdx.x;
    int bh = blockIdx.x;
    int b = bh >> 4, h = bh & 15;
    size_t base = (size_t)bh * SS * HD;
    for (int i = tid; i < SS*16; i += 256){
        int s = i >> 4, c4 = (i & 15) << 2;
        float4 kk = *(const float4*)(k + base + (size_t)s*64 + c4);
        float4 vv = *(const float4*)(v + base + (size_t)s*64 + c4);
        ks[s*SROW+c4] = kk.x; ks[s*SROW+c4+1] = kk.y; ks[s*SROW+c4+2] = kk.z; ks[s*SROW+c4+3] = kk.w;
        vs[s*SROW+c4] = vv.x; vs[s*SROW+c4+1] = vv.y; vs[s*SROW+c4+2] = vv.z; vs[s*SROW+c4+3] = vv.w;
    }
    __syncthreads();
    int c0 = cbase + (blockIdx.y << 8);
    int w = tid >> 5;
    for (int gI = 0; gI < 32; gI++){
        int cg = c0 + (gI << 3);
        #pragma unroll
        for (int p = 0; p < 2; p++){
            int i = tid + (p << 8);
            int ci = i >> 6, e = i & 63;
            qs2[e*8 + ci] = q[((size_t)h*CDIM + cg + ci)*64 + e];
        }
        __syncthreads();
        unsigned long long acc2[4] = {0ull, 0ull, 0ull, 0ull};
        #pragma unroll
        for (int e = 0; e < 64; e += 4){
            float4 kk = *(float4*)&ks[tid*SROW + e];
            float kcomp[4] = {kk.x, kk.y, kk.z, kk.w};
            #pragma unroll
            for (int j = 0; j < 4; j++){
                unsigned long long kd;
                PACK2(kd, kcomp[j], kcomp[j]);
                #pragma unroll
                for (int p = 0; p < 4; p++){
                    unsigned long long qp = *(unsigned long long*)&qs2[(e+j)*8 + 2*p];
                    FMA2(acc2[p], kd, qp, acc2[p]);
                }
            }
        }
        float sc[8];
        #pragma unroll
        for (int p = 0; p < 4; p++){
            UNPACK2(sc[2*p], sc[2*p+1], acc2[p]);
        }
        #pragma unroll
        for (int ci = 0; ci < 8; ci++) sc[ci] *= 0.125f;
        #pragma unroll
        for (int ci = 0; ci < 8; ci++){
            float m = warp_max(sc[ci]);
            if ((tid & 31) == 0) rd[ci*8 + w] = m;
        }
        __syncthreads();
        #pragma unroll
        for (int ci = 0; ci < 8; ci++){
            float bm = rd[ci*8];
            #pragma unroll
            for (int i = 1; i < 8; i++) bm = fmaxf(bm, rd[ci*8 + i]);
            float ex = __expf(sc[ci] - bm);
            at2[(ci >> 1)*512 + tid*2 + (ci & 1)] = ex;
            float ws = warp_sum(ex);
            if ((tid & 31) == 0) rd[64 + ci*8 + w] = ws;
        }
        __syncthreads();
        float inv[8];
        #pragma unroll
        for (int ci = 0; ci < 8; ci++){
            float bs = 0.f;
            #pragma unroll
            for (int i = 0; i < 8; i++) bs += rd[64 + ci*8 + i];
            inv[ci] = 1.f / bs;
        }
        {
            int e = tid & 63, ch = tid >> 6;
            unsigned long long vacc[4] = {0ull, 0ull, 0ull, 0ull};
            #pragma unroll 8
            for (int i = 0; i < 64; i++){
                int s = (ch << 6) + i;
                float vv = vs[s*SROW + e];
                unsigned long long vd;
                PACK2(vd, vv, vv);
                #pragma unroll
                for (int p = 0; p < 4; p++){
                    unsigned long long ad = *(unsigned long long*)&at2[p*512 + s*2];
                    FMA2(vacc[p], ad, vd, vacc[p]);
                }
            }
            #pragma unroll
            for (int p = 0; p < 4; p++){
                float a0, a1;
                UNPACK2(a0, a1, vacc[p]);
                op[(2*p)*256 + tid]   = a0;
                op[(2*p+1)*256 + tid] = a1;
            }
        }
        __syncthreads();
        #pragma unroll
        for (int p = 0; p < 2; p++){
            int i = tid + (p << 8);
            int ci = i >> 6, e = i & 63;
            float oo = (op[ci*256 + e] + op[ci*256 + 64 + e]
                      + op[ci*256 + 128 + e] + op[ci*256 + 192 + e]) * inv[ci];
            o[((size_t)b*CDIM + cg + ci)*ATT + h*64 + e] = oo;
        }
        __syncthreads();
    }
}

// ---------------- layernorm rows of 1024 -> fp16 (chunked) ----------------
__global__ void __launch_bounds__(256) ln_conv_kernel(const float* __restrict__ gamma,
                                                      const float* __restrict__ beta,
                                                      const float* __restrict__ in,
                                                      __half* __restrict__ hi, int cbase){
    __shared__ float rs[8], rq[8];
    int idx = blockIdx.x;
    int row = ((idx >> 11) << 12) + cbase + (idx & 2047);
    int tid = threadIdx.x;
    float4 v = ((const float4*)(in + (size_t)row*ATT))[tid];
    float s = v.x+v.y+v.z+v.w;
    float q = v.x*v.x+v.y*v.y+v.z*v.z+v.w*v.w;
    s = warp_sum(s); q = warp_sum(q);
    if ((tid & 31) == 0){ rs[tid>>5] = s; rq[tid>>5] = q; }
    __syncthreads();
    float ts = 0.f, tq = 0.f;
    #pragma unroll
    for (int i = 0; i < 8; i++){ ts += rs[i]; tq += rq[i]; }
    float mu = ts * (1.f/1024.f);
    float var = tq * (1.f/1024.f) - mu*mu;
    float rr = rsqrtf(var + EPSV);
    float4 g4 = ((const float4*)gamma)[tid];
    float4 b4 = ((const float4*)beta)[tid];
    __half h[4];
    h[0] = __float2half((v.x-mu)*rr*g4.x + b4.x);
    h[1] = __float2half((v.y-mu)*rr*g4.y + b4.y);
    h[2] = __float2half((v.z-mu)*rr*g4.z + b4.z);
    h[3] = __float2half((v.w-mu)*rr*g4.w + b4.w);
    *(uint2*)&hi[(size_t)row*ATT + tid*4] = *(uint2*)h;
}

// ---------------- final (chunked) ----------------
__global__ void __launch_bounds__(256) final_kernel(const float* __restrict__ ow,
                                                    const float* __restrict__ z,
                                                    float* __restrict__ out, int cbase){
    __shared__ float r0[8], r1[8];
    int idx = blockIdx.x;
    int row = ((idx >> 11) << 12) + cbase + (idx & 2047);
    int tid = threadIdx.x;
    int c = row & (CDIM-1);
    const float2* w = (const float2*)(ow + (size_t)c*2048);
    float a0 = 0.f, a1 = 0.f;
    #pragma unroll
    for (int it = 0; it < 4; it++){
        int a = tid + it*256;
        float zz = z[(size_t)row*ATT + a];
        float2 ww = w[a];
        a0 = fmaf(zz, ww.x, a0);
        a1 = fmaf(zz, ww.y, a1);
    }
    a0 = warp_sum(a0); a1 = warp_sum(a1);
    if ((tid & 31) == 0){ r0[tid>>5] = a0; r1[tid>>5] = a1; }
    __syncthreads();
    if (tid == 0){
        float y0 = 0.f, y1 = 0.f;
        #pragma unroll
        for (int i = 0; i < 8; i++){ y0 += r0[i]; y1 += r1[i]; }
        out[row] = y0 / (1.f + __expf(-y0)) * y1;
    }
}

// ---------------- launch ----------------
extern "C" void kernel_launch(void* const* d_in, const int* in_sizes, int n_in,
                              void* d_out, int out_size){
    const float* x        = (const float*)d_in[0];
    const float* cls      = (const float*)d_in[1];
    const float* roots    = (const float*)d_in[2];
    const float* cr_w     = (const float*)d_in[3];
    const float* cc_w     = (const float*)d_in[4];
    const float* kv_w     = (const float*)d_in[5];
    const float* ln_gamma = (const float*)d_in[6];
    const float* ln_beta  = (const float*)d_in[7];
    const float* ff_in_w  = (const float*)d_in[8];
    const float* ff_out_w = (const float*)d_in[9];
    const float* out_w    = (const float*)d_in[10];
    const int*   cr_idx   = (const int*)d_in[11];
    const int*   cc_idx   = (const int*)d_in[12];
    float* out = (float*)d_out;

    void *pq, *pqdet, *pqr, *pkvraw, *pk, *pv, *po, *pz;
    void *pxhi, *pxlo, *pkvwh, *pkvwl, *plnh, *pffinh, *pgh, *pffouth;
    cudaGetSymbolAddress(&pq, g_q);
    cudaGetSymbolAddress(&pqdet, g_qdet);
    cudaGetSymbolAddress(&pqr, g_qr);
    cudaGetSymbolAddress(&pkvraw, g_kvraw);
    cudaGetSymbolAddress(&pk, g_k);
    cudaGetSymbolAddress(&pv, g_v);
    cudaGetSymbolAddress(&po, g_o);
    cudaGetSymbolAddress(&pz, g_z);
    cudaGetSymbolAddress(&pxhi, g_xhi);     cudaGetSymbolAddress(&pxlo, g_xlo);
    cudaGetSymbolAddress(&pkvwh, g_kvwh);   cudaGetSymbolAddress(&pkvwl, g_kvwl);
    cudaGetSymbolAddress(&plnh, g_lnh);
    cudaGetSymbolAddress(&pffinh, g_ffinh);
    cudaGetSymbolAddress(&pgh, g_gh);
    cudaGetSymbolAddress(&pffouth, g_ffouth);

    static cudaStream_t s2 = nullptr, s3 = nullptr, sB = nullptr;
    static cudaEvent_t eb = nullptr, e_kvw, e_ffin, e_ffout, e_q, e_kv, e_a0, e_a1, e_t0;
    if (!eb){
        cudaStreamCreateWithFlags(&s2, cudaStreamNonBlocking);
        cudaStreamCreateWithFlags(&s3, cudaStreamNonBlocking);
        cudaStreamCreateWithFlags(&sB, cudaStreamNonBlocking);
        cudaEventCreateWithFlags(&eb,      cudaEventDisableTiming);
        cudaEventCreateWithFlags(&e_kvw,   cudaEventDisableTiming);
        cudaEventCreateWithFlags(&e_ffin,  cudaEventDisableTiming);
        cudaEventCreateWithFlags(&e_ffout, cudaEventDisableTiming);
        cudaEventCreateWithFlags(&e_q,     cudaEventDisableTiming);
        cudaEventCreateWithFlags(&e_kv,    cudaEventDisableTiming);
        cudaEventCreateWithFlags(&e_a0,    cudaEventDisableTiming);
        cudaEventCreateWithFlags(&e_a1,    cudaEventDisableTiming);
        cudaEventCreateWithFlags(&e_t0,    cudaEventDisableTiming);
        cudaFuncSetAttribute(attn_kernel, cudaFuncAttributeMaxDynamicSharedMemorySize, ATTN_SMEM);
        cudaFuncSetAttribute(gemm_kv, cudaFuncAttributeMaxDynamicSharedMemorySize, GEMM_SMEM_4);
        cudaFuncSetAttribute(gemm_nt_addo256, cudaFuncAttributeMaxDynamicSharedMemorySize, GEMM256_SMEM);
        cudaFuncSetAttribute(gemm_ff1_gate256, cudaFuncAttributeMaxDynamicSharedMemorySize, GEMM256_SMEM);
    }

    // fork
    cudaEventRecord(eb, 0);
    cudaStreamWaitEvent(s2, eb, 0);
    cudaStreamWaitEvent(s3, eb, 0);
    cudaStreamWaitEvent(sB, eb, 0);

    // ---- s3: q preparation chain ----
    copy4_kernel<<<(HNUM*CDIM*HD/4 + 255)/256, 256, 0, s3>>>((const float4*)cls, (float4*)pq, HNUM*CDIM*HD/4);
    rms64_kernel<<<HNUM*RR, 32, 0, s3>>>(roots, (float*)pqr);
    scatter_kernel<<<HNUM*CRN, 64, 0, s3>>>(cr_idx, cr_idx + CRN, cr_w, (const float*)pqr, (float*)pq, CRN, RR);
    copy4_kernel<<<(HNUM*CDIM*HD/4 + 255)/256, 256, 0, s3>>>((const float4*)pq, (float4*)pqdet, HNUM*CDIM*HD/4);
    scatter_kernel<<<HNUM*SCN, 64, 0, s3>>>(cc_idx, cc_idx + SCN, cc_w, (const float*)pqdet, (float*)pq, SCN, CDIM);
    rms64_kernel<<<HNUM*CDIM, 32, 0, s3>>>((const float*)pq, (float*)pq);

    // ---- s2: weight conversions ----
    split_kernel<<<(2*ATT*DIN/4 + 255)/256, 256, 0, s2>>>((const float4*)kv_w, (__half*)pkvwh,
                                                          (__half*)pkvwl, 2*ATT*DIN/4);
    cudaEventRecord(e_kvw, s2);
    conv_ffin_kernel<<<(2*FFN*ATT/4 + 255)/256, 256, 0, s2>>>((const float4*)ff_in_w, (__half*)pffinh,
                                                              2*FFN*ATT/4);
    cudaEventRecord(e_ffin, s2);
    conv_half_kernel<<<(ATT*FFN/4 + 255)/256, 256, 0, s2>>>((const float4*)ff_out_w, (__half*)pffouth,
                                                            ATT*FFN/4);
    cudaEventRecord(e_ffout, s2);

    // ---- default: kv chain ----
    split_kernel<<<(BB*SS*DIN/4 + 255)/256, 256>>>((const float4*)x, (__half*)pxhi,
                                                   (__half*)pxlo, BB*SS*DIN/4);
    cudaStreamWaitEvent(0, e_kvw, 0);
    gemm_kv<<<dim3(2*ATT/128, BB*SS/128), 256, GEMM_SMEM_4>>>(
        (const __half*)pxhi, (const __half*)pxlo,
        (const __half*)pkvwh, (const __half*)pkvwl,
        (float*)pkvraw, BB*SS, 2*ATT, DIN);
    kvsplit_kernel<<<BB*HNUM*SS, 32>>>((const float*)pkvraw, (float*)pk, (float*)pv);
    cudaEventRecord(e_kv, 0);

    // ---- s3: attention in 2 c-chunks (q-prep already ordered on s3) ----
    cudaStreamWaitEvent(s3, e_kv, 0);
    attn_kernel<<<dim3(BB*HNUM, CW/256), 256, ATTN_SMEM, s3>>>(
        (const float*)pq, (const float*)pk, (const float*)pv, (float*)po, 0);
    cudaEventRecord(e_a0, s3);
    attn_kernel<<<dim3(BB*HNUM, CW/256), 256, ATTN_SMEM, s3>>>(
        (const float*)pq, (const float*)pk, (const float*)pv, (float*)po, CW);
    cudaEventRecord(e_a1, s3);

    // ---- sB: tail chunk 0 ----
    cudaStreamWaitEvent(sB, e_a0, 0);
    cudaStreamWaitEvent(sB, e_ffin, 0);
    cudaStreamWaitEvent(sB, e_ffout, 0);
    ln_conv_kernel<<<BB*CW, 256, 0, sB>>>(ln_gamma, ln_beta, (const float*)po, (__half*)plnh, 0);
    gemm_ff1_gate256<<<dim3(2*FFN/256, BB*CW/128), 256, GEMM256_SMEM, sB>>>(
        (const __half*)plnh, (const __half*)pffinh, (__half*)pgh, 2*FFN, ATT, 0);
    gemm_nt_addo256<<<dim3(ATT/256, BB*CW/128), 256, GEMM256_SMEM, sB>>>(
        (const __half*)pgh, (const __half*)pffouth, (const float*)po, (float*)pz, ATT, FFN, 0);
    final_kernel<<<BB*CW, 256, 0, sB>>>(out_w, (const float*)pz, out, 0);
    cudaEventRecord(e_t0, sB);

    // ---- default: tail chunk 1 ----
    cudaStreamWaitEvent(0, e_a1, 0);
    cudaStreamWaitEvent(0, e_ffin, 0);
    cudaStreamWaitEvent(0, e_ffout, 0);
    ln_conv_kernel<<<BB*CW, 256>>>(ln_gamma, ln_beta, (const float*)po, (__half*)plnh, CW);
    gemm_ff1_gate256<<<dim3(2*FFN/256, BB*CW/128), 256, GEMM256_SMEM>>>(
        (const __half*)plnh, (const __half*)pffinh, (__half*)pgh, 2*FFN, ATT, CW);
    gemm_nt_addo256<<<dim3(ATT/256, BB*CW/128), 256, GEMM256_SMEM>>>(
        (const __half*)pgh, (const __half*)pffouth, (const float*)po, (float*)pz, ATT, FFN, CW);
    final_kernel<<<BB*CW, 256>>>(out_w, (const float*)pz, out, CW);

    // join
    cudaStreamWaitEvent(0, e_t0, 0);
}

// round 17
// speedup vs baseline: 1.0393x; 1.0393x over previous
#include <cuda_runtime.h>
#include <cuda_fp16.h>
#include <cstdint>
#include <math.h>

// ---------------- problem constants ----------------
#define HNUM 16
#define CDIM 4096
#define HD 64
#define BB 4
#define SS 256
#define DIN 1024
#define ATT 1024
#define RR 256
#define CRN 1024
#define SCN 2048
#define FFN 3072
#define EPSV 1e-5f

// ---------------- device scratch ----------------
__device__ __align__(16) float g_q[HNUM*CDIM*HD];
__device__ __align__(16) float g_qdet[HNUM*CDIM*HD];
__device__ __align__(16) float g_qr[HNUM*RR*HD];
__device__ __align__(16) float g_kvraw[BB*SS*2*ATT];
__device__ __align__(16) float g_k[BB*HNUM*SS*HD];
__device__ __align__(16) float g_v[BB*HNUM*SS*HD];
__device__ __align__(16) float g_o[BB*CDIM*ATT];
__device__ __align__(16) float g_z[BB*CDIM*ATT];

__device__ __align__(16) __half g_xhi[BB*SS*DIN],   g_xlo[BB*SS*DIN];
__device__ __align__(16) __half g_kvwh[2*ATT*DIN],  g_kvwl[2*ATT*DIN];
__device__ __align__(16) __half g_lnh[BB*CDIM*ATT];
__device__ __align__(16) __half g_ffinh[2*FFN*ATT];
__device__ __align__(16) __half g_gh[(size_t)BB*CDIM*FFN];
__device__ __align__(16) __half g_ffouth[ATT*FFN];

__device__ __forceinline__ float warp_sum(float v){
    #pragma unroll
    for (int o = 16; o; o >>= 1) v += __shfl_xor_sync(0xffffffffu, v, o);
    return v;
}
__device__ __forceinline__ float warp_max(float v){
    #pragma unroll
    for (int o = 16; o; o >>= 1) v = fmaxf(v, __shfl_xor_sync(0xffffffffu, v, o));
    return v;
}

// packed f32x2 helpers
#define PACK2(out, lo, hi) asm("mov.b64 %0, {%1, %2};" : "=l"(out) : "f"(lo), "f"(hi))
#define UNPACK2(lo, hi, in) asm("mov.b64 {%0, %1}, %2;" : "=f"(lo), "=f"(hi) : "l"(in))
#define FMA2(d, a, b, c) asm("fma.rn.f32x2 %0, %1, %2, %3;" : "=l"(d) : "l"(a), "l"(b), "l"(c))

__global__ void copy4_kernel(const float4* __restrict__ src, float4* __restrict__ dst, int n4){
    int i = blockIdx.x * blockDim.x + threadIdx.x;
    if (i < n4) dst[i] = src[i];
}

__global__ void split_kernel(const float4* __restrict__ in, __half* __restrict__ hi,
                             __half* __restrict__ lo, int n4){
    int i = blockIdx.x * blockDim.x + threadIdx.x;
    if (i >= n4) return;
    float4 v = in[i];
    float vv[4] = {v.x, v.y, v.z, v.w};
    __half h[4], l[4];
    #pragma unroll
    for (int j = 0; j < 4; j++){
        h[j] = __float2half(vv[j]);
        l[j] = __float2half(vv[j] - __half2float(h[j]));
    }
    *(uint2*)&hi[(size_t)i*4] = *(uint2*)h;
    *(uint2*)&lo[(size_t)i*4] = *(uint2*)l;
}

__global__ void conv_half_kernel(const float4* __restrict__ in, __half* __restrict__ out, int n4){
    int i = blockIdx.x * blockDim.x + threadIdx.x;
    if (i >= n4) return;
    float4 v = in[i];
    __half h[4] = {__float2half(v.x), __float2half(v.y), __float2half(v.z), __float2half(v.w)};
    *(uint2*)&out[(size_t)i*4] = *(uint2*)h;
}

__global__ void conv_ffin_kernel(const float4* __restrict__ in, __half* __restrict__ out, int n4){
    int i = blockIdx.x * blockDim.x + threadIdx.x;
    if (i >= n4) return;
    int e = i * 4;
    int rout = e >> 10;
    int c = e & 1023;
    int rin = (rout & 1) ? (FFN + (rout >> 1)) : (rout >> 1);
    float4 v = in[((size_t)rin << 10 | c) >> 2];
    __half h[4] = {__float2half(v.x), __float2half(v.y), __float2half(v.z), __float2half(v.w)};
    *(uint2*)&out[(size_t)rout*1024 + c] = *(uint2*)h;
}

__global__ void rms64_kernel(const float* __restrict__ in, float* __restrict__ out){
    int row = blockIdx.x, t = threadIdx.x;
    float2 v = ((const float2*)(in + (size_t)row*64))[t];
    float ss = v.x*v.x + v.y*v.y;
    ss = warp_sum(ss);
    float sc = rsqrtf(ss*(1.f/64.f) + EPSV);
    ((float2*)(out + (size_t)row*64))[t] = make_float2(v.x*sc, v.y*sc);
}

__global__ void scatter_kernel(const int* __restrict__ srcidx, const int* __restrict__ dstidx,
                               const float* __restrict__ w, const float* __restrict__ src,
                               float* __restrict__ dst, int nper, int src_rows){
    int j = blockIdx.x % nper;
    int h = blockIdx.x / nper;
    int r = srcidx[j];
    int c = dstidx[j];
    float ww = w[(size_t)h*nper + j];
    int t = threadIdx.x;
    atomicAdd(&dst[((size_t)h*CDIM + c)*64 + t], src[((size_t)h*src_rows + r)*64 + t] * ww);
}

__global__ void kvsplit_kernel(const float* __restrict__ kvraw, float* __restrict__ kout,
                               float* __restrict__ vout){
    int bid = blockIdx.x;
    int t = threadIdx.x;
    int b = bid >> 12, h = (bid >> 8) & 15, s = bid & 255;
    size_t rowoff = ((size_t)(b*SS + s))*2048 + h*64;
    float2 kv = ((const float2*)(kvraw + rowoff))[t];
    float2 vv = ((const float2*)(kvraw + rowoff + 1024))[t];
    float ss = kv.x*kv.x + kv.y*kv.y;
    ss = warp_sum(ss);
    float sc = rsqrtf(ss*(1.f/64.f) + EPSV);
    ((float2*)(kout + (size_t)bid*64))[t] = make_float2(kv.x*sc, kv.y*sc);
    ((float2*)(vout + (size_t)bid*64))[t] = vv;
}

// ---------------- common GEMM pieces ----------------
#define GR 40
#define BUF_BYTES (128*GR*2)
#define GEMM_SMEM_4 (2*4*BUF_BYTES)

__device__ __forceinline__ void mma16816(float* d, const unsigned int* a, const unsigned int* b){
    asm volatile(
        "mma.sync.aligned.m16n8k16.row.col.f32.f16.f16.f32 "
        "{%0,%1,%2,%3}, {%4,%5,%6,%7}, {%8,%9}, {%0,%1,%2,%3};\n"
        : "+f"(d[0]), "+f"(d[1]), "+f"(d[2]), "+f"(d[3])
        : "r"(a[0]), "r"(a[1]), "r"(a[2]), "r"(a[3]), "r"(b[0]), "r"(b[1]));
}
__device__ __forceinline__ void ldsm_x4(unsigned int& r0, unsigned int& r1,
                                        unsigned int& r2, unsigned int& r3, unsigned int addr){
    asm volatile("ldmatrix.sync.aligned.m8n8.x4.shared.b16 {%0,%1,%2,%3}, [%4];"
                 : "=r"(r0), "=r"(r1), "=r"(r2), "=r"(r3) : "r"(addr));
}
__device__ __forceinline__ void cpasync16(unsigned int saddr, const void* g){
    asm volatile("cp.async.cg.shared.global [%0], [%1], 16;" :: "r"(saddr), "l"(g));
}

// ---------------- kv GEMM: 3-product, 128x128 tile ----------------
__global__ void __launch_bounds__(256) gemm_kv(
    const __half* __restrict__ Ahi, const __half* __restrict__ Alo,
    const __half* __restrict__ Bhi, const __half* __restrict__ Blo,
    float* __restrict__ C, int M, int N, int K)
{
    extern __shared__ __half smem[];
    float acc[2][8][4] = {};
    const int tid = threadIdx.x;
    const int bm = blockIdx.y << 7, bn = blockIdx.x << 7;
    const int warp = tid >> 5, lane = tid & 31;
    const int g = lane >> 2, tg = lane & 3;
    const int wm = (warp >> 1) << 5, wn = (warp & 1) << 6;
    unsigned int sbase = (unsigned int)__cvta_generic_to_shared(smem);
    const __half* gah = Ahi + (size_t)bm*K;
    const __half* gal = Alo + (size_t)bm*K;
    const __half* gbh = Bhi + (size_t)bn*K;
    const __half* gbl = Blo + (size_t)bn*K;
    const int lr = tid >> 2, lc = (tid & 3) << 3;

    auto load_stage = [&](int k0, int s){
        unsigned int sb = sbase + s*4*BUF_BYTES;
        #pragma unroll
        for (int half_i = 0; half_i < 2; half_i++){
            int r = lr + (half_i << 6);
            size_t go = (size_t)r*K + k0 + lc;
            unsigned int so = (unsigned int)(r*GR + lc)*2;
            cpasync16(sb + so, gah + go);
            cpasync16(sb + 1*BUF_BYTES + so, gal + go);
            cpasync16(sb + 2*BUF_BYTES + so, gbh + go);
            cpasync16(sb + 3*BUF_BYTES + so, gbl + go);
        }
        asm volatile("cp.async.commit_group;");
    };

    load_stage(0, 0);
    const int nIt = K >> 5;
    for (int it = 0; it < nIt; it++){
        int s = it & 1;
        if (it + 1 < nIt){
            load_stage((it + 1) << 5, s ^ 1);
            asm volatile("cp.async.wait_group 1;");
        } else {
            asm volatile("cp.async.wait_group 0;");
        }
        __syncthreads();
        unsigned int sAh = sbase + (s*4 + 0)*BUF_BYTES;
        unsigned int sAl = sbase + (s*4 + 1)*BUF_BYTES;
        unsigned int sBh = sbase + (s*4 + 2)*BUF_BYTES;
        unsigned int sBl = sbase + (s*4 + 3)*BUF_BYTES;
        #pragma unroll
        for (int kg = 0; kg < 2; kg++){
            unsigned int ah[2][4], al[2][4];
            unsigned int aoff = (unsigned int)((wm + (lane & 15))*80 + kg*32 + ((lane >> 4) << 4));
            ldsm_x4(ah[0][0], ah[0][1], ah[0][2], ah[0][3], sAh + aoff);
            ldsm_x4(ah[1][0], ah[1][1], ah[1][2], ah[1][3], sAh + aoff + 16*80);
            ldsm_x4(al[0][0], al[0][1], al[0][2], al[0][3], sAl + aoff);
            ldsm_x4(al[1][0], al[1][1], al[1][2], al[1][3], sAl + aoff + 16*80);
            #pragma unroll
            for (int np = 0; np < 4; np++){
                unsigned int boff = (unsigned int)(
                    (wn + np*16 + (lane & 7) + ((lane >> 4) << 3))*80
                    + kg*32 + (((lane >> 3) & 1) << 4));
                unsigned int bh[4], bl[4];
                ldsm_x4(bh[0], bh[1], bh[2], bh[3], sBh + boff);
                ldsm_x4(bl[0], bl[1], bl[2], bl[3], sBl + boff);
                #pragma unroll
                for (int mt = 0; mt < 2; mt++){
                    mma16816(acc[mt][np*2], ah[mt], bh);
                    mma16816(acc[mt][np*2], al[mt], bh);
                    mma16816(acc[mt][np*2], ah[mt], bl);
                    mma16816(acc[mt][np*2 + 1], ah[mt], bh + 2);
                    mma16816(acc[mt][np*2 + 1], al[mt], bh + 2);
                    mma16816(acc[mt][np*2 + 1], ah[mt], bl + 2);
                }
            }
        }
        __syncthreads();
    }
    #pragma unroll
    for (int mt = 0; mt < 2; mt++){
        #pragma unroll
        for (int nt = 0; nt < 8; nt++){
            size_t row0 = (size_t)bm + wm + (mt << 4) + g;
            int col = bn + wn + (nt << 3) + (tg << 1);
            *(float2*)&C[row0*N + col]      = make_float2(acc[mt][nt][0], acc[mt][nt][1]);
            *(float2*)&C[(row0+8)*N + col]  = make_float2(acc[mt][nt][2], acc[mt][nt][3]);
        }
    }
}

// ---------------- single-product GEMM, 128x256 tile (FF1) ----------------
#define ABUF256 (128*GR*2)
#define BBUF256 (256*GR*2)
#define STG256 (ABUF256 + BBUF256)
#define GEMM256_SMEM (2*STG256)

__device__ __forceinline__ void gemm256_mainloop(
    const __half* __restrict__ Ah, const __half* __restrict__ Bh,
    int K, int bm, int bn, float acc[4][8][4], __half* smem)
{
    const int tid = threadIdx.x;
    const int warp = tid >> 5, lane = tid & 31;
    const int wm = (warp >> 2) << 6;
    const int wn = (warp & 3) << 6;
    unsigned int sbase = (unsigned int)__cvta_generic_to_shared(smem);
    const __half* ga = Ah + (size_t)bm*K;
    const __half* gb = Bh + (size_t)bn*K;
    const int lr = tid >> 2, lc = (tid & 3) << 3;

    auto load_stage = [&](int k0, int s){
        unsigned int sb = sbase + s*STG256;
        #pragma unroll
        for (int p = 0; p < 2; p++){
            int r = lr + (p << 6);
            size_t go = (size_t)r*K + k0 + lc;
            unsigned int so = (unsigned int)(r*GR + lc)*2;
            cpasync16(sb + so, ga + go);
        }
        #pragma unroll
        for (int p = 0; p < 4; p++){
            int r = lr + (p << 6);
            size_t go = (size_t)r*K + k0 + lc;
            unsigned int so = (unsigned int)(r*GR + lc)*2;
            cpasync16(sb + ABUF256 + so, gb + go);
        }
        asm volatile("cp.async.commit_group;");
    };

    load_stage(0, 0);
    const int nIt = K >> 5;
    for (int it = 0; it < nIt; it++){
        int s = it & 1;
        if (it + 1 < nIt){
            load_stage((it + 1) << 5, s ^ 1);
            asm volatile("cp.async.wait_group 1;");
        } else {
            asm volatile("cp.async.wait_group 0;");
        }
        __syncthreads();
        unsigned int sA = sbase + s*STG256;
        unsigned int sB = sA + ABUF256;
        #pragma unroll
        for (int kg = 0; kg < 2; kg++){
            unsigned int ah[4][4];
            unsigned int aoff = (unsigned int)((wm + (lane & 15))*80 + kg*32 + ((lane >> 4) << 4));
            ldsm_x4(ah[0][0], ah[0][1], ah[0][2], ah[0][3], sA + aoff);
            ldsm_x4(ah[1][0], ah[1][1], ah[1][2], ah[1][3], sA + aoff + 16*80);
            ldsm_x4(ah[2][0], ah[2][1], ah[2][2], ah[2][3], sA + aoff + 32*80);
            ldsm_x4(ah[3][0], ah[3][1], ah[3][2], ah[3][3], sA + aoff + 48*80);
            #pragma unroll
            for (int np = 0; np < 4; np++){
                unsigned int boff = (unsigned int)(
                    (wn + np*16 + (lane & 7) + ((lane >> 4) << 3))*80
                    + kg*32 + (((lane >> 3) & 1) << 4));
                unsigned int bh[4];
                ldsm_x4(bh[0], bh[1], bh[2], bh[3], sB + boff);
                #pragma unroll
                for (int mt = 0; mt < 4; mt++){
                    mma16816(acc[mt][np*2],     ah[mt], bh);
                    mma16816(acc[mt][np*2 + 1], ah[mt], bh + 2);
                }
            }
        }
        __syncthreads();
    }
}

#define GSR256 132
__global__ void __launch_bounds__(256) gemm_ff1_gate256(
    const __half* __restrict__ Ah, const __half* __restrict__ Bh,
    __half* __restrict__ Gh, int M, int N, int K)
{
    extern __shared__ __half smem[];
    float acc[4][8][4] = {};
    const int tid = threadIdx.x;
    const int bm = blockIdx.y << 7, bn = blockIdx.x << 8;
    const int warp = tid >> 5, lane = tid & 31;
    const int g = lane >> 2, tg = lane & 3;
    const int wm = (warp >> 2) << 6, wn = (warp & 3) << 6;
    gemm256_mainloop(Ah, Bh, K, bm, bn, acc, smem);
    __half* sh = smem;
    #pragma unroll
    for (int mt = 0; mt < 4; mt++){
        #pragma unroll
        for (int nt = 0; nt < 8; nt++){
            int rl = wm + (mt << 4) + g;
            int oc = (wn >> 1) + (nt << 2) + tg;
            float f1a = acc[mt][nt][0], f2a = acc[mt][nt][1];
            float f1b = acc[mt][nt][2], f2b = acc[mt][nt][3];
            float ga = f1a / (1.f + __expf(-f1a)) * f2a;
            float gb = f1b / (1.f + __expf(-f1b)) * f2b;
            sh[rl*GSR256 + oc]     = __float2half(ga);
            sh[(rl+8)*GSR256 + oc] = __float2half(gb);
        }
    }
    __syncthreads();
    int gc0 = bn >> 1;
    #pragma unroll
    for (int idx = tid; idx < 4096; idx += 256){
        int row = idx >> 5, c4 = (idx & 31) << 2;
        size_t go = (size_t)(bm + row)*FFN + gc0 + c4;
        *(uint2*)&Gh[go] = *(uint2*)&sh[row*GSR256 + c4];
    }
}

// ---------------- FF2: single-product 128x128 tile, 2 CTAs/SM, fused residual ----------------
#define STG128 (2*BUF_BYTES)          // A + B per stage = 20480
#define GEMM128_SMEM (2*STG128)       // 40960

__global__ void __launch_bounds__(256, 2) gemm_nt_addo128(
    const __half* __restrict__ Ah, const __half* __restrict__ Bh,
    const float* __restrict__ O,
    float* __restrict__ Z, int M, int N, int K)
{
    extern __shared__ __half smem[];
    float acc[2][8][4] = {};
    const int tid = threadIdx.x;
    const int bm = blockIdx.y << 7, bn = blockIdx.x << 7;
    const int warp = tid >> 5, lane = tid & 31;
    const int g = lane >> 2, tg = lane & 3;
    const int wm = (warp >> 1) << 5, wn = (warp & 1) << 6;
    unsigned int sbase = (unsigned int)__cvta_generic_to_shared(smem);
    const __half* ga = Ah + (size_t)bm*K;
    const __half* gb = Bh + (size_t)bn*K;
    const int lr = tid >> 2, lc = (tid & 3) << 3;

    auto load_stage = [&](int k0, int s){
        unsigned int sb = sbase + s*STG128;
        #pragma unroll
        for (int half_i = 0; half_i < 2; half_i++){
            int r = lr + (half_i << 6);
            size_t go = (size_t)r*K + k0 + lc;
            unsigned int so = (unsigned int)(r*GR + lc)*2;
            cpasync16(sb + so, ga + go);
            cpasync16(sb + BUF_BYTES + so, gb + go);
        }
        asm volatile("cp.async.commit_group;");
    };

    load_stage(0, 0);
    const int nIt = K >> 5;
    for (int it = 0; it < nIt; it++){
        int s = it & 1;
        if (it + 1 < nIt){
            load_stage((it + 1) << 5, s ^ 1);
            asm volatile("cp.async.wait_group 1;");
        } else {
            asm volatile("cp.async.wait_group 0;");
        }
        __syncthreads();
        unsigned int sA = sbase + s*STG128;
        unsigned int sB = sA + BUF_BYTES;
        #pragma unroll
        for (int kg = 0; kg < 2; kg++){
            unsigned int ah[2][4];
            unsigned int aoff = (unsigned int)((wm + (lane & 15))*80 + kg*32 + ((lane >> 4) << 4));
            ldsm_x4(ah[0][0], ah[0][1], ah[0][2], ah[0][3], sA + aoff);
            ldsm_x4(ah[1][0], ah[1][1], ah[1][2], ah[1][3], sA + aoff + 16*80);
            #pragma unroll
            for (int np = 0; np < 4; np++){
                unsigned int boff = (unsigned int)(
                    (wn + np*16 + (lane & 7) + ((lane >> 4) << 3))*80
                    + kg*32 + (((lane >> 3) & 1) << 4));
                unsigned int bh[4];
                ldsm_x4(bh[0], bh[1], bh[2], bh[3], sB + boff);
                #pragma unroll
                for (int mt = 0; mt < 2; mt++){
                    mma16816(acc[mt][np*2],     ah[mt], bh);
                    mma16816(acc[mt][np*2 + 1], ah[mt], bh + 2);
                }
            }
        }
        __syncthreads();
    }
    #pragma unroll
    for (int mt = 0; mt < 2; mt++){
        #pragma unroll
        for (int nt = 0; nt < 8; nt++){
            size_t row0 = (size_t)bm + wm + (mt << 4) + g;
            int col = bn + wn + (nt << 3) + (tg << 1);
            float2 o0 = *(const float2*)&O[row0*N + col];
            float2 o1 = *(const float2*)&O[(row0+8)*N + col];
            *(float2*)&Z[row0*N + col]     = make_float2(acc[mt][nt][0] + o0.x, acc[mt][nt][1] + o0.y);
            *(float2*)&Z[(row0+8)*N + col] = make_float2(acc[mt][nt][2] + o1.x, acc[mt][nt][3] + o1.y);
        }
    }
}

// ---------------- attention: 8 c per iter, f32x2 packed FMA ----------------
#define SROW 68
#define ATTN_SMEM ((2*256*SROW + 512 + 2048 + 2048 + 128) * 4)
__global__ void __launch_bounds__(256) attn_kernel(const float* __restrict__ q,
                                                   const float* __restrict__ k,
                                                   const float* __restrict__ v,
                                                   float* __restrict__ o){
    extern __shared__ float sm[];
    float* ks = sm;
    float* vs = ks + 256*SROW;
    float* qs2 = vs + 256*SROW;
    float* at2 = qs2 + 512;
    float* op  = at2 + 2048;
    float* rd  = op + 2048;
    int tid = threadIdx.x;
    int bh = blockIdx.x;
    int b = bh >> 4, h = bh & 15;
    size_t base = (size_t)bh * SS * HD;
    for (int i = tid; i < SS*16; i += 256){
        int s = i >> 4, c4 = (i & 15) << 2;
        float4 kk = *(const float4*)(k + base + (size_t)s*64 + c4);
        float4 vv = *(const float4*)(v + base + (size_t)s*64 + c4);
        ks[s*SROW+c4] = kk.x; ks[s*SROW+c4+1] = kk.y; ks[s*SROW+c4+2] = kk.z; ks[s*SROW+c4+3] = kk.w;
        vs[s*SROW+c4] = vv.x; vs[s*SROW+c4+1] = vv.y; vs[s*SROW+c4+2] = vv.z; vs[s*SROW+c4+3] = vv.w;
    }
    __syncthreads();
    int c0 = blockIdx.y << 8;
    int w = tid >> 5;
    for (int gI = 0; gI < 32; gI++){
        int cg = c0 + (gI << 3);
        #pragma unroll
        for (int p = 0; p < 2; p++){
            int i = tid + (p << 8);
            int ci = i >> 6, e = i & 63;
            qs2[e*8 + ci] = q[((size_t)h*CDIM + cg + ci)*64 + e];
        }
        __syncthreads();
        unsigned long long acc2[4] = {0ull, 0ull, 0ull, 0ull};
        #pragma unroll
        for (int e = 0; e < 64; e += 4){
            float4 kk = *(float4*)&ks[tid*SROW + e];
            float kcomp[4] = {kk.x, kk.y, kk.z, kk.w};
            #pragma unroll
            for (int j = 0; j < 4; j++){
                unsigned long long kd;
                PACK2(kd, kcomp[j], kcomp[j]);
                #pragma unroll
                for (int p = 0; p < 4; p++){
                    unsigned long long qp = *(unsigned long long*)&qs2[(e+j)*8 + 2*p];
                    FMA2(acc2[p], kd, qp, acc2[p]);
                }
            }
        }
        float sc[8];
        #pragma unroll
        for (int p = 0; p < 4; p++){
            UNPACK2(sc[2*p], sc[2*p+1], acc2[p]);
        }
        #pragma unroll
        for (int ci = 0; ci < 8; ci++) sc[ci] *= 0.125f;
        #pragma unroll
        for (int ci = 0; ci < 8; ci++){
            float m = warp_max(sc[ci]);
            if ((tid & 31) == 0) rd[ci*8 + w] = m;
        }
        __syncthreads();
        #pragma unroll
        for (int ci = 0; ci < 8; ci++){
            float bm = rd[ci*8];
            #pragma unroll
            for (int i = 1; i < 8; i++) bm = fmaxf(bm, rd[ci*8 + i]);
            float ex = __expf(sc[ci] - bm);
            at2[(ci >> 1)*512 + tid*2 + (ci & 1)] = ex;
            float ws = warp_sum(ex);
            if ((tid & 31) == 0) rd[64 + ci*8 + w] = ws;
        }
        __syncthreads();
        float inv[8];
        #pragma unroll
        for (int ci = 0; ci < 8; ci++){
            float bs = 0.f;
            #pragma unroll
            for (int i = 0; i < 8; i++) bs += rd[64 + ci*8 + i];
            inv[ci] = 1.f / bs;
        }
        {
            int e = tid & 63, ch = tid >> 6;
            unsigned long long vacc[4] = {0ull, 0ull, 0ull, 0ull};
            #pragma unroll 8
            for (int i = 0; i < 64; i++){
                int s = (ch << 6) + i;
                float vv = vs[s*SROW + e];
                unsigned long long vd;
                PACK2(vd, vv, vv);
                #pragma unroll
                for (int p = 0; p < 4; p++){
                    unsigned long long ad = *(unsigned long long*)&at2[p*512 + s*2];
                    FMA2(vacc[p], ad, vd, vacc[p]);
                }
            }
            #pragma unroll
            for (int p = 0; p < 4; p++){
                float a0, a1;
                UNPACK2(a0, a1, vacc[p]);
                op[(2*p)*256 + tid]   = a0;
                op[(2*p+1)*256 + tid] = a1;
            }
        }
        __syncthreads();
        #pragma unroll
        for (int p = 0; p < 2; p++){
            int i = tid + (p << 8);
            int ci = i >> 6, e = i & 63;
            float oo = (op[ci*256 + e] + op[ci*256 + 64 + e]
                      + op[ci*256 + 128 + e] + op[ci*256 + 192 + e]) * inv[ci];
            o[((size_t)b*CDIM + cg + ci)*ATT + h*64 + e] = oo;
        }
        __syncthreads();
    }
}

// ---------------- layernorm rows of 1024 -> fp16 ----------------
__global__ void __launch_bounds__(256) ln_conv_kernel(const float* __restrict__ gamma,
                                                      const float* __restrict__ beta,
                                                      const float* __restrict__ in,
                                                      __half* __restrict__ hi){
    __shared__ float rs[8], rq[8];
    int row = blockIdx.x, tid = threadIdx.x;
    float4 v = ((const float4*)(in + (size_t)row*ATT))[tid];
    float s = v.x+v.y+v.z+v.w;
    float q = v.x*v.x+v.y*v.y+v.z*v.z+v.w*v.w;
    s = warp_sum(s); q = warp_sum(q);
    if ((tid & 31) == 0){ rs[tid>>5] = s; rq[tid>>5] = q; }
    __syncthreads();
    float ts = 0.f, tq = 0.f;
    #pragma unroll
    for (int i = 0; i < 8; i++){ ts += rs[i]; tq += rq[i]; }
    float mu = ts * (1.f/1024.f);
    float var = tq * (1.f/1024.f) - mu*mu;
    float rr = rsqrtf(var + EPSV);
    float4 g4 = ((const float4*)gamma)[tid];
    float4 b4 = ((const float4*)beta)[tid];
    __half h[4];
    h[0] = __float2half((v.x-mu)*rr*g4.x + b4.x);
    h[1] = __float2half((v.y-mu)*rr*g4.y + b4.y);
    h[2] = __float2half((v.z-mu)*rr*g4.z + b4.z);
    h[3] = __float2half((v.w-mu)*rr*g4.w + b4.w);
    *(uint2*)&hi[(size_t)row*ATT + tid*4] = *(uint2*)h;
}

// ---------------- final ----------------
__global__ void __launch_bounds__(256) final_kernel(const float* __restrict__ ow,
                                                    const float* __restrict__ z,
                                                    float* __restrict__ out){
    __shared__ float r0[8], r1[8];
    int row = blockIdx.x, tid = threadIdx.x;
    int c = row & (CDIM-1);
    const float2* w = (const float2*)(ow + (size_t)c*2048);
    float a0 = 0.f, a1 = 0.f;
    #pragma unroll
    for (int it = 0; it < 4; it++){
        int a = tid + it*256;
        float zz = z[(size_t)row*ATT + a];
        float2 ww = w[a];
        a0 = fmaf(zz, ww.x, a0);
        a1 = fmaf(zz, ww.y, a1);
    }
    a0 = warp_sum(a0); a1 = warp_sum(a1);
    if ((tid & 31) == 0){ r0[tid>>5] = a0; r1[tid>>5] = a1; }
    __syncthreads();
    if (tid == 0){
        float y0 = 0.f, y1 = 0.f;
        #pragma unroll
        for (int i = 0; i < 8; i++){ y0 += r0[i]; y1 += r1[i]; }
        out[row] = y0 / (1.f + __expf(-y0)) * y1;
    }
}

// ---------------- launch ----------------
extern "C" void kernel_launch(void* const* d_in, const int* in_sizes, int n_in,
                              void* d_out, int out_size){
    const float* x        = (const float*)d_in[0];
    const float* cls      = (const float*)d_in[1];
    const float* roots    = (const float*)d_in[2];
    const float* cr_w     = (const float*)d_in[3];
    const float* cc_w     = (const float*)d_in[4];
    const float* kv_w     = (const float*)d_in[5];
    const float* ln_gamma = (const float*)d_in[6];
    const float* ln_beta  = (const float*)d_in[7];
    const float* ff_in_w  = (const float*)d_in[8];
    const float* ff_out_w = (const float*)d_in[9];
    const float* out_w    = (const float*)d_in[10];
    const int*   cr_idx   = (const int*)d_in[11];
    const int*   cc_idx   = (const int*)d_in[12];
    float* out = (float*)d_out;

    void *pq, *pqdet, *pqr, *pkvraw, *pk, *pv, *po, *pz;
    void *pxhi, *pxlo, *pkvwh, *pkvwl, *plnh, *pffinh, *pgh, *pffouth;
    cudaGetSymbolAddress(&pq, g_q);
    cudaGetSymbolAddress(&pqdet, g_qdet);
    cudaGetSymbolAddress(&pqr, g_qr);
    cudaGetSymbolAddress(&pkvraw, g_kvraw);
    cudaGetSymbolAddress(&pk, g_k);
    cudaGetSymbolAddress(&pv, g_v);
    cudaGetSymbolAddress(&po, g_o);
    cudaGetSymbolAddress(&pz, g_z);
    cudaGetSymbolAddress(&pxhi, g_xhi);     cudaGetSymbolAddress(&pxlo, g_xlo);
    cudaGetSymbolAddress(&pkvwh, g_kvwh);   cudaGetSymbolAddress(&pkvwl, g_kvwl);
    cudaGetSymbolAddress(&plnh, g_lnh);
    cudaGetSymbolAddress(&pffinh, g_ffinh);
    cudaGetSymbolAddress(&pgh, g_gh);
    cudaGetSymbolAddress(&pffouth, g_ffouth);

    // one-time resources (created on the uncaptured correctness call)
    static cudaStream_t s2 = nullptr, s3 = nullptr;
    static cudaEvent_t eb = nullptr, e_kvw, e_ffin, e_ffout, e_q;
    if (!eb){
        cudaStreamCreateWithFlags(&s2, cudaStreamNonBlocking);
        cudaStreamCreateWithFlags(&s3, cudaStreamNonBlocking);
        cudaEventCreateWithFlags(&eb,      cudaEventDisableTiming);
        cudaEventCreateWithFlags(&e_kvw,   cudaEventDisableTiming);
        cudaEventCreateWithFlags(&e_ffin,  cudaEventDisableTiming);
        cudaEventCreateWithFlags(&e_ffout, cudaEventDisableTiming);
        cudaEventCreateWithFlags(&e_q,     cudaEventDisableTiming);
        cudaFuncSetAttribute(attn_kernel, cudaFuncAttributeMaxDynamicSharedMemorySize, ATTN_SMEM);
        cudaFuncSetAttribute(gemm_kv, cudaFuncAttributeMaxDynamicSharedMemorySize, GEMM_SMEM_4);
        cudaFuncSetAttribute(gemm_nt_addo128, cudaFuncAttributeMaxDynamicSharedMemorySize, GEMM128_SMEM);
        cudaFuncSetAttribute(gemm_ff1_gate256, cudaFuncAttributeMaxDynamicSharedMemorySize, GEMM256_SMEM);
    }

    // fork
    cudaEventRecord(eb, 0);
    cudaStreamWaitEvent(s2, eb, 0);
    cudaStreamWaitEvent(s3, eb, 0);

    // ---- s3: q preparation chain ----
    copy4_kernel<<<(HNUM*CDIM*HD/4 + 255)/256, 256, 0, s3>>>((const float4*)cls, (float4*)pq, HNUM*CDIM*HD/4);
    rms64_kernel<<<HNUM*RR, 32, 0, s3>>>(roots, (float*)pqr);
    scatter_kernel<<<HNUM*CRN, 64, 0, s3>>>(cr_idx, cr_idx + CRN, cr_w, (const float*)pqr, (float*)pq, CRN, RR);
    copy4_kernel<<<(HNUM*CDIM*HD/4 + 255)/256, 256, 0, s3>>>((const float4*)pq, (float4*)pqdet, HNUM*CDIM*HD/4);
    scatter_kernel<<<HNUM*SCN, 64, 0, s3>>>(cc_idx, cc_idx + SCN, cc_w, (const float*)pqdet, (float*)pq, SCN, CDIM);
    rms64_kernel<<<HNUM*CDIM, 32, 0, s3>>>((const float*)pq, (float*)pq);
    cudaEventRecord(e_q, s3);

    // ---- s2: weight conversions ----
    split_kernel<<<(2*ATT*DIN/4 + 255)/256, 256, 0, s2>>>((const float4*)kv_w, (__half*)pkvwh,
                                                          (__half*)pkvwl, 2*ATT*DIN/4);
    cudaEventRecord(e_kvw, s2);
    conv_ffin_kernel<<<(2*FFN*ATT/4 + 255)/256, 256, 0, s2>>>((const float4*)ff_in_w, (__half*)pffinh,
                                                              2*FFN*ATT/4);
    cudaEventRecord(e_ffin, s2);
    conv_half_kernel<<<(ATT*FFN/4 + 255)/256, 256, 0, s2>>>((const float4*)ff_out_w, (__half*)pffouth,
                                                            ATT*FFN/4);
    cudaEventRecord(e_ffout, s2);

    // ---- default stream: main chain ----
    split_kernel<<<(BB*SS*DIN/4 + 255)/256, 256>>>((const float4*)x, (__half*)pxhi,
                                                   (__half*)pxlo, BB*SS*DIN/4);
    cudaStreamWaitEvent(0, e_kvw, 0);
    gemm_kv<<<dim3(2*ATT/128, BB*SS/128), 256, GEMM_SMEM_4>>>(
        (const __half*)pxhi, (const __half*)pxlo,
        (const __half*)pkvwh, (const __half*)pkvwl,
        (float*)pkvraw, BB*SS, 2*ATT, DIN);
    kvsplit_kernel<<<BB*HNUM*SS, 32>>>((const float*)pkvraw, (float*)pk, (float*)pv);

    cudaStreamWaitEvent(0, e_q, 0);
    attn_kernel<<<dim3(BB*HNUM, CDIM/256), 256, ATTN_SMEM>>>((const float*)pq, (const float*)pk,
                                                             (const float*)pv, (float*)po);

    ln_conv_kernel<<<BB*CDIM, 256>>>(ln_gamma, ln_beta, (const float*)po, (__half*)plnh);

    cudaStreamWaitEvent(0, e_ffin, 0);
    gemm_ff1_gate256<<<dim3(2*FFN/256, BB*CDIM/128), 256, GEMM256_SMEM>>>(
        (const __half*)plnh, (const __half*)pffinh,
        (__half*)pgh, BB*CDIM, 2*FFN, ATT);

    cudaStreamWaitEvent(0, e_ffout, 0);
    gemm_nt_addo128<<<dim3(ATT/128, BB*CDIM/128), 256, GEMM128_SMEM>>>(
        (const __half*)pgh, (const __half*)pffouth, (const float*)po,
        (float*)pz, BB*CDIM, ATT, FFN);

    final_kernel<<<BB*CDIM, 256>>>(out_w, (const float*)pz, out);
}